// round 1
// baseline (speedup 1.0000x reference)
#include <cuda_runtime.h>
#include <cstdint>

#define Bn 128
#define Ln 512
#define En 512
#define Hn 256
#define G4 1024
#define Kn 64

// ---------------- scratch (static device allocations) ----------------
__device__ float g_preT[2][Ln][G4][Bn];       // 536 MB: pre-activations, transposed [dir][t][gate_col][b]
__device__ float g_hT[2][2][Hn][Bn];          // h state double-buffered: [parity][dir][k][b]
__device__ float g_hist[Ln][Bn][2*Hn];        // 134 MB: concat hidden states [t][b][2H]
__device__ float g_emit[Bn][Ln][Kn];          // 16.7 MB: emissions [b][t][k]
__device__ unsigned long long g_bar[32];      // spin-barrier counters (monotonic across replays)

__device__ __forceinline__ float sigf(float x) {
    return 1.0f / (1.0f + __expf(-x));
}
__device__ __forceinline__ float tanhfast(float x) {
    float e = __expf(2.0f * x);
    return 1.0f - __fdividef(2.0f, e + 1.0f);
}

// ---------------- 1) input GEMM: pre = x @ W_ih^T + b_ih + b_hh ----------------
// C tile: 128(b of one t) x 128(gate cols), K=512, fp32. Output transposed: g_preT[dir][t][g][b].
__global__ void __launch_bounds__(256) k_gemm_in(
    const float* __restrict__ x,
    const float* __restrict__ wf, const float* __restrict__ wb,
    const float* __restrict__ bihf, const float* __restrict__ bhhf,
    const float* __restrict__ bihb, const float* __restrict__ bhhb)
{
    const int ntile = blockIdx.x;           // 0..7
    const int t     = blockIdx.y;           // 0..511
    const int dir   = blockIdx.z;           // 0,1
    const float* __restrict__ W = dir ? wb : wf;
    const int t_eff = dir ? (Ln - 1 - t) : t;

    __shared__ float As[16][132];
    __shared__ float Bs[16][132];
    const int tid = threadIdx.x;
    const int tm = (tid >> 4) << 3;         // row (b) base
    const int tn = (tid & 15) << 3;         // col base within tile

    float acc[8][8];
#pragma unroll
    for (int i = 0; i < 8; i++)
#pragma unroll
        for (int j = 0; j < 8; j++) acc[i][j] = 0.0f;

    for (int k0 = 0; k0 < En; k0 += 16) {
#pragma unroll
        for (int i = 0; i < 2; i++) {
            int idx = tid + (i << 8);
            int r  = idx >> 2;              // 0..127
            int kk = (idx & 3) << 2;        // 0,4,8,12
            float4 va = *(const float4*)(x + ((size_t)r * Ln + t_eff) * En + k0 + kk);
            As[kk + 0][r] = va.x; As[kk + 1][r] = va.y;
            As[kk + 2][r] = va.z; As[kk + 3][r] = va.w;
            float4 vb = *(const float4*)(W + ((size_t)(ntile * 128 + r)) * En + k0 + kk);
            Bs[kk + 0][r] = vb.x; Bs[kk + 1][r] = vb.y;
            Bs[kk + 2][r] = vb.z; Bs[kk + 3][r] = vb.w;
        }
        __syncthreads();
#pragma unroll
        for (int kk = 0; kk < 16; kk++) {
            float a[8], bv[8];
            *(float4*)(a)      = *(float4*)&As[kk][tm];
            *(float4*)(a + 4)  = *(float4*)&As[kk][tm + 4];
            *(float4*)(bv)     = *(float4*)&Bs[kk][tn];
            *(float4*)(bv + 4) = *(float4*)&Bs[kk][tn + 4];
#pragma unroll
            for (int i = 0; i < 8; i++)
#pragma unroll
                for (int j = 0; j < 8; j++)
                    acc[i][j] = fmaf(a[i], bv[j], acc[i][j]);
        }
        __syncthreads();
    }

    const float* __restrict__ bih = dir ? bihb : bihf;
    const float* __restrict__ bhh = dir ? bhhb : bhhf;
#pragma unroll
    for (int j = 0; j < 8; j++) {
        int g = ntile * 128 + tn + j;
        float bias = bih[g] + bhh[g];
        float v[8];
#pragma unroll
        for (int i = 0; i < 8; i++) v[i] = acc[i][j] + bias;
        float* dst = &g_preT[dir][t][g][tm];
        *(float4*)dst       = *(float4*)v;
        *(float4*)(dst + 4) = *(float4*)(v + 4);
    }
}

// ---------------- 2) LSTM recurrence: persistent, gate-sliced, grid spin-barrier ----------------
// 128 CTAs: dir = blk>>6, slice = blk&63 (4 hidden units). W_hh slice (16 cols x 256) lives in SMEM.
// Per step: G[128b][16col] = preT + H(128x256) @ Wslice; then gate update for 4 hidden units x 128 b.
__global__ void __launch_bounds__(128) k_lstm(
    const float* __restrict__ whf, const float* __restrict__ whb)
{
    const int dir   = blockIdx.x >> 6;
    const int slice = blockIdx.x & 63;
    const int m0    = slice << 2;
    const float* __restrict__ whh = dir ? whb : whf;
    const int tid = threadIdx.x;

    __shared__ float Ws[256][16];   // [k][gate*4+m]
    __shared__ float hs[32][128];   // staged h block [kk][b]
    __shared__ float Gs[16][128];   // gates [gate*4+m][b]
    __shared__ float cs[4][128];    // cell state [m][b]

    // load W slice once (16 gate columns x 256 k, transposed)
    {
        int cc = tid >> 3;               // 0..15
        int kc = (tid & 7) << 5;         // 0,32,..,224
        int gate = cc >> 2, m = cc & 3;
        int gcol = gate * 256 + m0 + m;
#pragma unroll
        for (int i = 0; i < 32; i += 4) {
            float4 w = *(const float4*)(whh + (size_t)gcol * Hn + kc + i);
            Ws[kc + i + 0][cc] = w.x; Ws[kc + i + 1][cc] = w.y;
            Ws[kc + i + 2][cc] = w.z; Ws[kc + i + 3][cc] = w.w;
        }
    }
#pragma unroll
    for (int i = 0; i < 4; i++) cs[i][tid] = 0.0f;
    __syncthreads();

    const int c4 = tid >> 5;        // gate (phase1) / hidden m (phase2)
    const int bq = tid & 31;        // batch quad
    const int b4 = bq << 2;
    volatile unsigned long long* barp = &g_bar[dir * 8];

    for (int t = 0; t < Ln; t++) {
        float acc[4][4];
#pragma unroll
        for (int m = 0; m < 4; m++) {
            float4 p = *(const float4*)&g_preT[dir][t][c4 * 256 + m0 + m][b4];
            acc[m][0] = p.x; acc[m][1] = p.y; acc[m][2] = p.z; acc[m][3] = p.w;
        }
        if (t > 0) {
            const int rp = (t & 1) ^ 1;       // parity of h(t-1)
#pragma unroll 1
            for (int kb = 0; kb < 8; kb++) {
#pragma unroll
                for (int i = 0; i < 8; i++) {
                    int idx = (i << 7) + tid;      // float4 index 0..1023
                    int kk  = idx >> 5;
                    int bb  = (idx & 31) << 2;
                    float4 hv = __ldcg((const float4*)&g_hT[rp][dir][(kb << 5) + kk][bb]);
                    *(float4*)&hs[kk][bb] = hv;
                }
                __syncthreads();
#pragma unroll
                for (int kk = 0; kk < 32; kk++) {
                    float4 w4 = *(float4*)&Ws[(kb << 5) + kk][c4 << 2];
                    float4 h4 = *(float4*)&hs[kk][b4];
                    float w[4] = {w4.x, w4.y, w4.z, w4.w};
                    float hh[4] = {h4.x, h4.y, h4.z, h4.w};
#pragma unroll
                    for (int m = 0; m < 4; m++)
#pragma unroll
                        for (int bi = 0; bi < 4; bi++)
                            acc[m][bi] = fmaf(w[m], hh[bi], acc[m][bi]);
                }
                __syncthreads();
            }
        }
        // publish gates to smem
#pragma unroll
        for (int m = 0; m < 4; m++)
            *(float4*)&Gs[(c4 << 2) + m][b4] =
                make_float4(acc[m][0], acc[m][1], acc[m][2], acc[m][3]);
        __syncthreads();

        // phase 2: gate update; thread owns hidden unit mm=c4, batches b4..b4+3
        {
            const int mm = c4;
            float4 gi = *(float4*)&Gs[0 + mm][b4];
            float4 gf = *(float4*)&Gs[4 + mm][b4];
            float4 gg = *(float4*)&Gs[8 + mm][b4];
            float4 go = *(float4*)&Gs[12 + mm][b4];
            float4 c  = *(float4*)&cs[mm][b4];
            float4 h;
            c.x = sigf(gf.x) * c.x + sigf(gi.x) * tanhfast(gg.x); h.x = sigf(go.x) * tanhfast(c.x);
            c.y = sigf(gf.y) * c.y + sigf(gi.y) * tanhfast(gg.y); h.y = sigf(go.y) * tanhfast(c.y);
            c.z = sigf(gf.z) * c.z + sigf(gi.z) * tanhfast(gg.z); h.z = sigf(go.z) * tanhfast(c.z);
            c.w = sigf(gf.w) * c.w + sigf(gi.w) * tanhfast(gg.w); h.w = sigf(go.w) * tanhfast(c.w);
            *(float4*)&cs[mm][b4] = c;
            __stcg((float4*)&g_hT[t & 1][dir][m0 + mm][b4], h);
            const int rt  = dir ? (Ln - 1 - t) : t;
            const int col = dir * 256 + m0 + mm;
            g_hist[rt][b4 + 0][col] = h.x;
            g_hist[rt][b4 + 1][col] = h.y;
            g_hist[rt][b4 + 2][col] = h.z;
            g_hist[rt][b4 + 3][col] = h.w;
        }

        if (t != Ln - 1) {
            __threadfence();
            __syncthreads();
            if (tid == 0) {
                unsigned long long v = atomicAdd(&g_bar[dir * 8], 1ULL);
                unsigned long long target = ((v >> 6) + 1ULL) << 6;   // 64 CTAs per direction
                while (*barp < target) __nanosleep(128);
            }
            __syncthreads();
        }
    }
}

// ---------------- 3) emit GEMM: emit[b][t][k] = hist[t][b][:512] @ w_emit^T + b_emit ----------------
__global__ void __launch_bounds__(256) k_emit(
    const float* __restrict__ wem, const float* __restrict__ bem)
{
    const int t = blockIdx.x;
    __shared__ float As[128][36];  // [b][jj]
    __shared__ float Bs[32][68];   // [jj][k]
    const int tid = threadIdx.x;
    const int kg = (tid & 7) << 3;   // k base (8 per thread)
    const int bg = (tid >> 3) << 2;  // b base (4 per thread)

    float acc[4][8];
#pragma unroll
    for (int i = 0; i < 4; i++)
#pragma unroll
        for (int j = 0; j < 8; j++) acc[i][j] = 0.0f;

    for (int j0 = 0; j0 < 512; j0 += 32) {
#pragma unroll
        for (int i = 0; i < 4; i++) {
            int idx = (i << 8) + tid;        // f4 idx 0..1023
            int b   = idx >> 3;
            int jj  = (idx & 7) << 2;
            float4 v = *(const float4*)&g_hist[t][b][j0 + jj];
            *(float4*)&As[b][jj] = v;
        }
#pragma unroll
        for (int i = 0; i < 2; i++) {
            int idx = (i << 8) + tid;        // f4 idx 0..511
            int k   = idx >> 3;
            int jj  = (idx & 7) << 2;
            float4 w = *(const float4*)(wem + (size_t)k * 512 + j0 + jj);
            Bs[jj + 0][k] = w.x; Bs[jj + 1][k] = w.y;
            Bs[jj + 2][k] = w.z; Bs[jj + 3][k] = w.w;
        }
        __syncthreads();
#pragma unroll
        for (int jj = 0; jj < 32; jj++) {
            float a[4];
#pragma unroll
            for (int i = 0; i < 4; i++) a[i] = As[bg + i][jj];
            float w[8];
            *(float4*)(w)     = *(float4*)&Bs[jj][kg];
            *(float4*)(w + 4) = *(float4*)&Bs[jj][kg + 4];
#pragma unroll
            for (int i = 0; i < 4; i++)
#pragma unroll
                for (int k = 0; k < 8; k++)
                    acc[i][k] = fmaf(a[i], w[k], acc[i][k]);
        }
        __syncthreads();
    }
#pragma unroll
    for (int i = 0; i < 4; i++) {
        float v[8];
#pragma unroll
        for (int k = 0; k < 8; k++) v[k] = acc[i][k] + bem[kg + k];
        float* dst = &g_emit[bg + i][t][kg];
        *(float4*)dst       = *(float4*)v;
        *(float4*)(dst + 4) = *(float4*)(v + 4);
    }
}

// ---------------- 4) CRF forward + gold score ----------------
// d'[j] = e[t][j] + m + log( sum_i exp(d[i]-m) * expT[i][j] ), expT precomputed in SMEM.
__global__ void __launch_bounds__(64) k_crf(
    const int* __restrict__ labels,
    const float* __restrict__ trans,
    float* __restrict__ out)
{
    const int b = blockIdx.x;
    const int j = threadIdx.x;
    const int lane = j & 31, wid = j >> 5;
    __shared__ float eT[64][64];
    __shared__ float ps[64];
    __shared__ float red[2];

#pragma unroll 8
    for (int i = 0; i < 64; i++)
        eT[i][j] = __expf(trans[i * 64 + j]);
    __syncthreads();

    float d = g_emit[b][0][j];
    for (int t = 1; t < Ln; t++) {
        float m = d;
#pragma unroll
        for (int o = 16; o > 0; o >>= 1)
            m = fmaxf(m, __shfl_xor_sync(0xffffffffu, m, o));
        if (lane == 0) red[wid] = m;
        __syncthreads();
        m = fmaxf(red[0], red[1]);
        float p = __expf(d - m);
        ps[j] = p;
        __syncthreads();
        float s = 0.0f;
#pragma unroll 16
        for (int i = 0; i < 64; i++) s = fmaf(ps[i], eT[i][j], s);
        d = g_emit[b][t][j] + m + __logf(s);
        __syncthreads();
    }

    // log_z = logsumexp(d)
    float m2 = d;
#pragma unroll
    for (int o = 16; o > 0; o >>= 1)
        m2 = fmaxf(m2, __shfl_xor_sync(0xffffffffu, m2, o));
    if (lane == 0) red[wid] = m2;
    __syncthreads();
    m2 = fmaxf(red[0], red[1]);
    __syncthreads();
    float sp = __expf(d - m2);
#pragma unroll
    for (int o = 16; o > 0; o >>= 1)
        sp += __shfl_xor_sync(0xffffffffu, sp, o);
    if (lane == 0) red[wid] = sp;
    __syncthreads();
    float logz = m2 + __logf(red[0] + red[1]);
    __syncthreads();

    // gold path score
    float gold = 0.0f;
    for (int t = j; t < Ln; t += 64) {
        int lab = labels[b * Ln + t];
        gold += g_emit[b][t][lab];
        if (t < Ln - 1) {
            int lab2 = labels[b * Ln + t + 1];
            gold += trans[lab * 64 + lab2];
        }
    }
#pragma unroll
    for (int o = 16; o > 0; o >>= 1)
        gold += __shfl_xor_sync(0xffffffffu, gold, o);
    if (lane == 0) red[wid] = gold;
    __syncthreads();
    gold = red[0] + red[1];

    if (j == 0) out[b] = logz - gold;
}

// ---------------- launch ----------------
extern "C" void kernel_launch(void* const* d_in, const int* in_sizes, int n_in,
                              void* d_out, int out_size)
{
    const float* x     = (const float*)d_in[0];
    const int*   lab   = (const int*)d_in[1];
    const float* wihf  = (const float*)d_in[2];
    const float* whhf  = (const float*)d_in[3];
    const float* bihf  = (const float*)d_in[4];
    const float* bhhf  = (const float*)d_in[5];
    const float* wihb  = (const float*)d_in[6];
    const float* whhb  = (const float*)d_in[7];
    const float* bihb  = (const float*)d_in[8];
    const float* bhhb  = (const float*)d_in[9];
    const float* wem   = (const float*)d_in[10];
    const float* bem   = (const float*)d_in[11];
    const float* trans = (const float*)d_in[12];
    float* out = (float*)d_out;

    dim3 gg(8, 512, 2);
    k_gemm_in<<<gg, 256>>>(x, wihf, wihb, bihf, bhhf, bihb, bhhb);
    k_lstm<<<128, 128>>>(whhf, whhb);
    k_emit<<<512, 256>>>(wem, bem);
    k_crf<<<128, 64>>>(lab, trans, out);
}

// round 3
// speedup vs baseline: 1.1998x; 1.1998x over previous
#include <cuda_runtime.h>
#include <cstdint>

#define Bn 128
#define Ln 512
#define En 512
#define Hn 256
#define G4 1024
#define Kn 64

// ---------------- scratch (static device allocations) ----------------
__device__ float g_preT[2][Ln][G4][Bn];       // pre-activations, transposed [dir][t][gate_col][b]
__device__ float g_hT[2][2][Hn][Bn];          // h state double-buffered: [parity][dir][k][b]
__device__ float g_hist[Ln][Bn][2*Hn];        // concat hidden states [t][b][2H]
__device__ float g_emit[Bn][Ln][Kn];          // emissions [b][t][k]
__device__ unsigned long long g_bar[32];      // spin-barrier counters (monotonic across replays)

__device__ __forceinline__ float sigf(float x) {
    return 1.0f / (1.0f + __expf(-x));
}
__device__ __forceinline__ float tanhfast(float x) {
    float e = __expf(2.0f * x);
    return 1.0f - __fdividef(2.0f, e + 1.0f);
}

__device__ __forceinline__ uint32_t f2tf32(float x) {
    uint32_t r;
    asm("cvt.rna.tf32.f32 %0, %1;" : "=r"(r) : "f"(x));
    return r;
}
__device__ __forceinline__ void mma_tf32(float* d, const uint32_t* a, const uint32_t* b) {
    asm volatile(
        "mma.sync.aligned.m16n8k8.row.col.f32.tf32.tf32.f32 "
        "{%0,%1,%2,%3}, {%4,%5,%6,%7}, {%8,%9}, {%0,%1,%2,%3};"
        : "+f"(d[0]), "+f"(d[1]), "+f"(d[2]), "+f"(d[3])
        : "r"(a[0]), "r"(a[1]), "r"(a[2]), "r"(a[3]), "r"(b[0]), "r"(b[1]));
}

// ---------------- 1) input GEMM (mma.sync tf32): pre = x @ W_ih^T + b_ih + b_hh ----------------
// C tile 128(gates M) x 128(batch N), K=512 in 16 stages of 32.
// 8 warps: warp_m = wid>>2 (2 blocks of 64 rows), warp_n = wid&3 (4 blocks of 32 cols).
// Each warp: 4x4 m16n8k8 fragments.
__global__ void __launch_bounds__(256) k_gemm_in_mma(
    const float* __restrict__ x,
    const float* __restrict__ wf, const float* __restrict__ wb,
    const float* __restrict__ bihf, const float* __restrict__ bhhf,
    const float* __restrict__ bihb, const float* __restrict__ bhhb)
{
    const int gtile = blockIdx.x;           // 0..7
    const int t     = blockIdx.y;           // 0..511
    const int dir   = blockIdx.z;           // 0,1
    const float* __restrict__ W = dir ? wb : wf;
    const int t_eff = dir ? (Ln - 1 - t) : t;
    const int g0 = gtile * 128;

    __shared__ uint32_t As[32][132];   // [k][m] tf32 bits
    __shared__ uint32_t Bs[32][132];   // [k][n] tf32 bits

    const int tid  = threadIdx.x;
    const int wid  = tid >> 5;
    const int lane = tid & 31;
    const int wm   = (wid >> 2) * 64;   // warp M base
    const int wn   = (wid & 3) * 32;    // warp N base
    const int grp  = lane >> 2;         // 0..7
    const int qk   = lane & 3;          // 0..3

    float acc[4][4][4];                 // [mi][ni][reg]
#pragma unroll
    for (int mi = 0; mi < 4; mi++)
#pragma unroll
        for (int ni = 0; ni < 4; ni++)
#pragma unroll
            for (int r = 0; r < 4; r++) acc[mi][ni][r] = 0.0f;

    for (int k0 = 0; k0 < En; k0 += 32) {
        // load A (W rows = gates) and B (x rows = batch): 128 rows x 32 k each
#pragma unroll
        for (int i = 0; i < 4; i++) {
            int idx = (i << 8) + tid;        // 0..1023 float4 slots
            int r   = idx >> 3;              // row 0..127
            int kk  = (idx & 7) << 2;        // k offset 0,4,..,28
            float4 va = *(const float4*)(W + (size_t)(g0 + r) * En + k0 + kk);
            As[kk + 0][r] = f2tf32(va.x); As[kk + 1][r] = f2tf32(va.y);
            As[kk + 2][r] = f2tf32(va.z); As[kk + 3][r] = f2tf32(va.w);
            float4 vb = *(const float4*)(x + ((size_t)r * Ln + t_eff) * En + k0 + kk);
            Bs[kk + 0][r] = f2tf32(vb.x); Bs[kk + 1][r] = f2tf32(vb.y);
            Bs[kk + 2][r] = f2tf32(vb.z); Bs[kk + 3][r] = f2tf32(vb.w);
        }
        __syncthreads();
#pragma unroll
        for (int kc = 0; kc < 32; kc += 8) {
            uint32_t af[4][4];    // [mi][reg]
            uint32_t bf[4][2];    // [ni][reg]
#pragma unroll
            for (int mi = 0; mi < 4; mi++) {
                int m = wm + mi * 16 + grp;
                af[mi][0] = As[kc + qk][m];
                af[mi][1] = As[kc + qk][m + 8];
                af[mi][2] = As[kc + qk + 4][m];
                af[mi][3] = As[kc + qk + 4][m + 8];
            }
#pragma unroll
            for (int ni = 0; ni < 4; ni++) {
                int n = wn + ni * 8 + grp;
                bf[ni][0] = Bs[kc + qk][n];
                bf[ni][1] = Bs[kc + qk + 4][n];
            }
#pragma unroll
            for (int mi = 0; mi < 4; mi++)
#pragma unroll
                for (int ni = 0; ni < 4; ni++)
                    mma_tf32(acc[mi][ni], af[mi], bf[ni]);
        }
        __syncthreads();
    }

    // epilogue: c0,c1 -> (row, n),(row, n+1); c2,c3 -> row+8
    const float* __restrict__ bih = dir ? bihb : bihf;
    const float* __restrict__ bhh = dir ? bhhb : bhhf;
#pragma unroll
    for (int mi = 0; mi < 4; mi++) {
        int r0 = wm + mi * 16 + grp;      // accumulate rows r0, r0+8
        int gA = g0 + r0;
        int gB = g0 + r0 + 8;
        float biasA = bih[gA] + bhh[gA];
        float biasB = bih[gB] + bhh[gB];
#pragma unroll
        for (int ni = 0; ni < 4; ni++) {
            int n = wn + ni * 8 + qk * 2;
            float2 vA = make_float2(acc[mi][ni][0] + biasA, acc[mi][ni][1] + biasA);
            float2 vB = make_float2(acc[mi][ni][2] + biasB, acc[mi][ni][3] + biasB);
            *(float2*)&g_preT[dir][t][gA][n] = vA;
            *(float2*)&g_preT[dir][t][gB][n] = vB;
        }
    }
}

// ---------------- 2) LSTM recurrence: persistent, gate-sliced, grid spin-barrier ----------------
__global__ void __launch_bounds__(128) k_lstm(
    const float* __restrict__ whf, const float* __restrict__ whb)
{
    const int dir   = blockIdx.x >> 6;
    const int slice = blockIdx.x & 63;
    const int m0    = slice << 2;
    const float* __restrict__ whh = dir ? whb : whf;
    const int tid = threadIdx.x;

    __shared__ float Ws[256][16];   // [k][gate*4+m]
    __shared__ float hs[32][128];   // staged h block [kk][b]
    __shared__ float Gs[16][128];   // gates [gate*4+m][b]
    __shared__ float cs[4][128];    // cell state [m][b]

    {
        int cc = tid >> 3;
        int kc = (tid & 7) << 5;
        int gate = cc >> 2, m = cc & 3;
        int gcol = gate * 256 + m0 + m;
#pragma unroll
        for (int i = 0; i < 32; i += 4) {
            float4 w = *(const float4*)(whh + (size_t)gcol * Hn + kc + i);
            Ws[kc + i + 0][cc] = w.x; Ws[kc + i + 1][cc] = w.y;
            Ws[kc + i + 2][cc] = w.z; Ws[kc + i + 3][cc] = w.w;
        }
    }
#pragma unroll
    for (int i = 0; i < 4; i++) cs[i][tid] = 0.0f;
    __syncthreads();

    const int c4 = tid >> 5;
    const int bq = tid & 31;
    const int b4 = bq << 2;
    volatile unsigned long long* barp = &g_bar[dir * 8];

    for (int t = 0; t < Ln; t++) {
        float acc[4][4];
#pragma unroll
        for (int m = 0; m < 4; m++) {
            float4 p = *(const float4*)&g_preT[dir][t][c4 * 256 + m0 + m][b4];
            acc[m][0] = p.x; acc[m][1] = p.y; acc[m][2] = p.z; acc[m][3] = p.w;
        }
        if (t > 0) {
            const int rp = (t & 1) ^ 1;
#pragma unroll 1
            for (int kb = 0; kb < 8; kb++) {
#pragma unroll
                for (int i = 0; i < 8; i++) {
                    int idx = (i << 7) + tid;
                    int kk  = idx >> 5;
                    int bb  = (idx & 31) << 2;
                    float4 hv = __ldcg((const float4*)&g_hT[rp][dir][(kb << 5) + kk][bb]);
                    *(float4*)&hs[kk][bb] = hv;
                }
                __syncthreads();
#pragma unroll
                for (int kk = 0; kk < 32; kk++) {
                    float4 w4 = *(float4*)&Ws[(kb << 5) + kk][c4 << 2];
                    float4 h4 = *(float4*)&hs[kk][b4];
                    float w[4] = {w4.x, w4.y, w4.z, w4.w};
                    float hh[4] = {h4.x, h4.y, h4.z, h4.w};
#pragma unroll
                    for (int m = 0; m < 4; m++)
#pragma unroll
                        for (int bi = 0; bi < 4; bi++)
                            acc[m][bi] = fmaf(w[m], hh[bi], acc[m][bi]);
                }
                __syncthreads();
            }
        }
#pragma unroll
        for (int m = 0; m < 4; m++)
            *(float4*)&Gs[(c4 << 2) + m][b4] =
                make_float4(acc[m][0], acc[m][1], acc[m][2], acc[m][3]);
        __syncthreads();

        {
            const int mm = c4;
            float4 gi = *(float4*)&Gs[0 + mm][b4];
            float4 gf = *(float4*)&Gs[4 + mm][b4];
            float4 gg = *(float4*)&Gs[8 + mm][b4];
            float4 go = *(float4*)&Gs[12 + mm][b4];
            float4 c  = *(float4*)&cs[mm][b4];
            float4 h;
            c.x = sigf(gf.x) * c.x + sigf(gi.x) * tanhfast(gg.x); h.x = sigf(go.x) * tanhfast(c.x);
            c.y = sigf(gf.y) * c.y + sigf(gi.y) * tanhfast(gg.y); h.y = sigf(go.y) * tanhfast(c.y);
            c.z = sigf(gf.z) * c.z + sigf(gi.z) * tanhfast(gg.z); h.z = sigf(go.z) * tanhfast(c.z);
            c.w = sigf(gf.w) * c.w + sigf(gi.w) * tanhfast(gg.w); h.w = sigf(go.w) * tanhfast(c.w);
            *(float4*)&cs[mm][b4] = c;
            __stcg((float4*)&g_hT[t & 1][dir][m0 + mm][b4], h);
            const int rt  = dir ? (Ln - 1 - t) : t;
            const int col = dir * 256 + m0 + mm;
            g_hist[rt][b4 + 0][col] = h.x;
            g_hist[rt][b4 + 1][col] = h.y;
            g_hist[rt][b4 + 2][col] = h.z;
            g_hist[rt][b4 + 3][col] = h.w;
        }

        if (t != Ln - 1) {
            __threadfence();
            __syncthreads();
            if (tid == 0) {
                unsigned long long v = atomicAdd(&g_bar[dir * 8], 1ULL);
                unsigned long long target = ((v >> 6) + 1ULL) << 6;
                while (*barp < target) __nanosleep(128);
            }
            __syncthreads();
        }
    }
}

// ---------------- 3) emit GEMM ----------------
__global__ void __launch_bounds__(256) k_emit(
    const float* __restrict__ wem, const float* __restrict__ bem)
{
    const int t = blockIdx.x;
    __shared__ float As[128][36];
    __shared__ float Bs[32][68];
    const int tid = threadIdx.x;
    const int kg = (tid & 7) << 3;
    const int bg = (tid >> 3) << 2;

    float acc[4][8];
#pragma unroll
    for (int i = 0; i < 4; i++)
#pragma unroll
        for (int j = 0; j < 8; j++) acc[i][j] = 0.0f;

    for (int j0 = 0; j0 < 512; j0 += 32) {
#pragma unroll
        for (int i = 0; i < 4; i++) {
            int idx = (i << 8) + tid;
            int b   = idx >> 3;
            int jj  = (idx & 7) << 2;
            float4 v = *(const float4*)&g_hist[t][b][j0 + jj];
            *(float4*)&As[b][jj] = v;
        }
#pragma unroll
        for (int i = 0; i < 2; i++) {
            int idx = (i << 8) + tid;
            int k   = idx >> 3;
            int jj  = (idx & 7) << 2;
            float4 w = *(const float4*)(wem + (size_t)k * 512 + j0 + jj);
            Bs[jj + 0][k] = w.x; Bs[jj + 1][k] = w.y;
            Bs[jj + 2][k] = w.z; Bs[jj + 3][k] = w.w;
        }
        __syncthreads();
#pragma unroll
        for (int jj = 0; jj < 32; jj++) {
            float a[4];
#pragma unroll
            for (int i = 0; i < 4; i++) a[i] = As[bg + i][jj];
            float w[8];
            *(float4*)(w)     = *(float4*)&Bs[jj][kg];
            *(float4*)(w + 4) = *(float4*)&Bs[jj][kg + 4];
#pragma unroll
            for (int i = 0; i < 4; i++)
#pragma unroll
                for (int k = 0; k < 8; k++)
                    acc[i][k] = fmaf(a[i], w[k], acc[i][k]);
        }
        __syncthreads();
    }
#pragma unroll
    for (int i = 0; i < 4; i++) {
        float v[8];
#pragma unroll
        for (int k = 0; k < 8; k++) v[k] = acc[i][k] + bem[kg + k];
        float* dst = &g_emit[bg + i][t][kg];
        *(float4*)dst       = *(float4*)v;
        *(float4*)(dst + 4) = *(float4*)(v + 4);
    }
}

// ---------------- 4) CRF forward + gold score ----------------
__global__ void __launch_bounds__(64) k_crf(
    const int* __restrict__ labels,
    const float* __restrict__ trans,
    float* __restrict__ out)
{
    const int b = blockIdx.x;
    const int j = threadIdx.x;
    const int lane = j & 31, wid = j >> 5;
    __shared__ float eT[64][64];
    __shared__ float ps[64];
    __shared__ float red[2];

#pragma unroll 8
    for (int i = 0; i < 64; i++)
        eT[i][j] = __expf(trans[i * 64 + j]);
    __syncthreads();

    float d = g_emit[b][0][j];
    for (int t = 1; t < Ln; t++) {
        float m = d;
#pragma unroll
        for (int o = 16; o > 0; o >>= 1)
            m = fmaxf(m, __shfl_xor_sync(0xffffffffu, m, o));
        if (lane == 0) red[wid] = m;
        __syncthreads();
        m = fmaxf(red[0], red[1]);
        float p = __expf(d - m);
        ps[j] = p;
        __syncthreads();
        float s0 = 0.0f, s1 = 0.0f, s2 = 0.0f, s3 = 0.0f;
#pragma unroll
        for (int i = 0; i < 64; i += 4) {
            s0 = fmaf(ps[i + 0], eT[i + 0][j], s0);
            s1 = fmaf(ps[i + 1], eT[i + 1][j], s1);
            s2 = fmaf(ps[i + 2], eT[i + 2][j], s2);
            s3 = fmaf(ps[i + 3], eT[i + 3][j], s3);
        }
        float s = (s0 + s1) + (s2 + s3);
        d = g_emit[b][t][j] + m + __logf(s);
        __syncthreads();
    }

    float m2 = d;
#pragma unroll
    for (int o = 16; o > 0; o >>= 1)
        m2 = fmaxf(m2, __shfl_xor_sync(0xffffffffu, m2, o));
    if (lane == 0) red[wid] = m2;
    __syncthreads();
    m2 = fmaxf(red[0], red[1]);
    __syncthreads();
    float sp = __expf(d - m2);
#pragma unroll
    for (int o = 16; o > 0; o >>= 1)
        sp += __shfl_xor_sync(0xffffffffu, sp, o);
    if (lane == 0) red[wid] = sp;
    __syncthreads();
    float logz = m2 + __logf(red[0] + red[1]);
    __syncthreads();

    float gold = 0.0f;
    for (int t = j; t < Ln; t += 64) {
        int lab = labels[b * Ln + t];
        gold += g_emit[b][t][lab];
        if (t < Ln - 1) {
            int lab2 = labels[b * Ln + t + 1];
            gold += trans[lab * 64 + lab2];
        }
    }
#pragma unroll
    for (int o = 16; o > 0; o >>= 1)
        gold += __shfl_xor_sync(0xffffffffu, gold, o);
    if (lane == 0) red[wid] = gold;
    __syncthreads();
    gold = red[0] + red[1];

    if (j == 0) out[b] = logz - gold;
}

// ---------------- launch ----------------
extern "C" void kernel_launch(void* const* d_in, const int* in_sizes, int n_in,
                              void* d_out, int out_size)
{
    const float* x     = (const float*)d_in[0];
    const int*   lab   = (const int*)d_in[1];
    const float* wihf  = (const float*)d_in[2];
    const float* whhf  = (const float*)d_in[3];
    const float* bihf  = (const float*)d_in[4];
    const float* bhhf  = (const float*)d_in[5];
    const float* wihb  = (const float*)d_in[6];
    const float* whhb  = (const float*)d_in[7];
    const float* bihb  = (const float*)d_in[8];
    const float* bhhb  = (const float*)d_in[9];
    const float* wem   = (const float*)d_in[10];
    const float* bem   = (const float*)d_in[11];
    const float* trans = (const float*)d_in[12];
    float* out = (float*)d_out;

    dim3 gg(8, 512, 2);
    k_gemm_in_mma<<<gg, 256>>>(x, wihf, wihb, bihf, bhhf, bihb, bhhb);
    k_lstm<<<128, 128>>>(whhf, whhb);
    k_emit<<<512, 256>>>(wem, bem);
    k_crf<<<128, 64>>>(lab, trans, out);
}

// round 4
// speedup vs baseline: 2.0882x; 1.7405x over previous
#include <cuda_runtime.h>
#include <cstdint>

#define Bn 128
#define Ln 512
#define En 512
#define Hn 256
#define G4 1024
#define Kn 64

// ---------------- scratch (static device allocations) ----------------
__device__ uint32_t g_preB[2][Ln][Bn][G4/2];   // 268MB: pre-activations bf16x2 [dir][t][b][gate_pair]
__device__ uint32_t g_hN[2][2][Hn/2][Bn];      // h state bf16x2, double-buffered [parity][dir][m_pair][b]
__device__ float g_hist[Ln][Bn][2*Hn];         // 134MB: concat hidden states fp32 [t][b][2H]
__device__ float g_emit[Bn][Ln][Kn];           // emissions [b][t][k]
__device__ unsigned long long g_bar[32];       // spin-barrier counters (monotonic across replays)

__device__ __forceinline__ float sigf(float x) {
    return 1.0f / (1.0f + __expf(-x));
}
__device__ __forceinline__ float tanhfast(float x) {
    float e = __expf(2.0f * x);
    return 1.0f - __fdividef(2.0f, e + 1.0f);
}

__device__ __forceinline__ uint32_t pack_bf16(float lo, float hi) {
    uint32_t r;
    asm("cvt.rn.bf16x2.f32 %0, %1, %2;" : "=r"(r) : "f"(hi), "f"(lo));
    return r;
}
__device__ __forceinline__ float bflo(uint32_t w) { return __uint_as_float(w << 16); }
__device__ __forceinline__ float bfhi(uint32_t w) { return __uint_as_float(w & 0xffff0000u); }

__device__ __forceinline__ void mma_bf16(float* d, const uint32_t* a, const uint32_t* b) {
    asm volatile(
        "mma.sync.aligned.m16n8k16.row.col.f32.bf16.bf16.f32 "
        "{%0,%1,%2,%3}, {%4,%5,%6,%7}, {%8,%9}, {%0,%1,%2,%3};"
        : "+f"(d[0]), "+f"(d[1]), "+f"(d[2]), "+f"(d[3])
        : "r"(a[0]), "r"(a[1]), "r"(a[2]), "r"(a[3]), "r"(b[0]), "r"(b[1]));
}

// ---------------- 1) input GEMM (mma.sync bf16): pre = x @ W_ih^T + b_ih + b_hh ----------------
// C tile: M=128 batch x N=128 gates, K=512 in 16 stages of 32.
// Output packed bf16x2 along gates: g_preB[dir][t][b][g2].
__global__ void __launch_bounds__(256) k_gemm_bf16(
    const float* __restrict__ x,
    const float* __restrict__ wf, const float* __restrict__ wb,
    const float* __restrict__ bihf, const float* __restrict__ bhhf,
    const float* __restrict__ bihb, const float* __restrict__ bhhb)
{
    const int gtile = blockIdx.x;           // 0..7
    const int t     = blockIdx.y;           // 0..511
    const int dir   = blockIdx.z;           // 0,1
    const float* __restrict__ W = dir ? wb : wf;
    const int t_eff = dir ? (Ln - 1 - t) : t;
    const int g0 = gtile * 128;

    __shared__ uint32_t As[16][136];   // [k2][b]  bf16x2 (x)
    __shared__ uint32_t Bs[16][136];   // [k2][g]  bf16x2 (W)

    const int tid  = threadIdx.x;
    const int wid  = tid >> 5;
    const int lane = tid & 31;
    const int wm   = (wid >> 2) * 64;   // warp M (batch) base
    const int wn   = (wid & 3) * 32;    // warp N (gate) base
    const int grp  = lane >> 2;         // 0..7
    const int qk   = lane & 3;          // 0..3

    float acc[4][4][4];                 // [mi][ni][reg]
#pragma unroll
    for (int mi = 0; mi < 4; mi++)
#pragma unroll
        for (int ni = 0; ni < 4; ni++)
#pragma unroll
            for (int r = 0; r < 4; r++) acc[mi][ni][r] = 0.0f;

    for (int k0 = 0; k0 < En; k0 += 32) {
#pragma unroll
        for (int i = 0; i < 4; i++) {
            int idx = (i << 8) + tid;        // 0..1023
            int r   = idx >> 3;              // row 0..127
            int f4  = idx & 7;               // float4 slot
            int k2  = f4 * 2;
            float4 va = *(const float4*)(x + ((size_t)r * Ln + t_eff) * En + k0 + f4 * 4);
            As[k2][r]     = pack_bf16(va.x, va.y);
            As[k2 + 1][r] = pack_bf16(va.z, va.w);
            float4 vb = *(const float4*)(W + (size_t)(g0 + r) * En + k0 + f4 * 4);
            Bs[k2][r]     = pack_bf16(vb.x, vb.y);
            Bs[k2 + 1][r] = pack_bf16(vb.z, vb.w);
        }
        __syncthreads();
#pragma unroll
        for (int kc2 = 0; kc2 < 16; kc2 += 8) {
            uint32_t af[4][4];    // [mi][reg]
            uint32_t bf[4][2];    // [ni][reg]
#pragma unroll
            for (int mi = 0; mi < 4; mi++) {
                int m = wm + mi * 16 + grp;
                af[mi][0] = As[kc2 + qk][m];
                af[mi][1] = As[kc2 + qk][m + 8];
                af[mi][2] = As[kc2 + 4 + qk][m];
                af[mi][3] = As[kc2 + 4 + qk][m + 8];
            }
#pragma unroll
            for (int ni = 0; ni < 4; ni++) {
                int n = wn + ni * 8 + grp;
                bf[ni][0] = Bs[kc2 + qk][n];
                bf[ni][1] = Bs[kc2 + 4 + qk][n];
            }
#pragma unroll
            for (int mi = 0; mi < 4; mi++)
#pragma unroll
                for (int ni = 0; ni < 4; ni++)
                    mma_bf16(acc[mi][ni], af[mi], bf[ni]);
        }
        __syncthreads();
    }

    // epilogue: c0,c1 = (row b, gates 2qk,2qk+1); c2,c3 = row b+8
    const float* __restrict__ bih = dir ? bihb : bihf;
    const float* __restrict__ bhh = dir ? bhhb : bhhf;
#pragma unroll
    for (int ni = 0; ni < 4; ni++) {
        int gate0 = g0 + wn + ni * 8 + 2 * qk;
        float bias0 = bih[gate0] + bhh[gate0];
        float bias1 = bih[gate0 + 1] + bhh[gate0 + 1];
        int g2w = (g0 + wn + ni * 8) / 2 + qk;
#pragma unroll
        for (int mi = 0; mi < 4; mi++) {
            int bA = wm + mi * 16 + grp;
            g_preB[dir][t][bA][g2w]     = pack_bf16(acc[mi][ni][0] + bias0, acc[mi][ni][1] + bias1);
            g_preB[dir][t][bA + 8][g2w] = pack_bf16(acc[mi][ni][2] + bias0, acc[mi][ni][3] + bias1);
        }
    }
}

// ---------------- 2) LSTM recurrence: persistent, gate-sliced, mma bf16 ----------------
// 128 CTAs x 256 threads. dir = blk>>6, slice = blk&63 (4 hidden units -> 16 gate cols, order type*4+ml).
// Per step per warp (owns 16 batch rows): C[16b x 16g] = h[16x256] @ Wslice[256x16] via 32 m16n8k16 mma.
// W_hh slice lives in registers (B-fragments, loaded once). h broadcast via global bf16x2 [k2][b].
__global__ void __launch_bounds__(256) k_lstm2(
    const float* __restrict__ whf, const float* __restrict__ whb)
{
    const int dir   = blockIdx.x >> 6;
    const int slice = blockIdx.x & 63;
    const int m0    = slice << 2;
    const float* __restrict__ whh = dir ? whb : whf;

    const int tid  = threadIdx.x;
    const int wid  = tid >> 5;
    const int lane = tid & 31;
    const int grp  = lane >> 2;
    const int qk   = lane & 3;
    const int bm   = wid * 16;          // warp's batch-row base

    // ---- B fragments (W_hh slice), persistent in registers ----
    uint32_t B0[2][16], B1[2][16];
#pragma unroll
    for (int nt = 0; nt < 2; nt++) {
        int c = nt * 8 + grp;                         // slice col 0..15
        int gcol = (c >> 2) * 256 + m0 + (c & 3);     // global gate
        const float* wr = whh + (size_t)gcol * Hn;
#pragma unroll
        for (int kb = 0; kb < 16; kb++) {
            float2 w0 = *(const float2*)(wr + kb * 16 + 2 * qk);
            float2 w1 = *(const float2*)(wr + kb * 16 + 8 + 2 * qk);
            B0[nt][kb] = pack_bf16(w0.x, w0.y);
            B1[nt][kb] = pack_bf16(w1.x, w1.y);
        }
    }

    float cst0 = 0.0f, cst1 = 0.0f;                   // cell state (2 per lane)
    const int rb      = (qk >= 2) ? 2 : 0;            // which acc regs this lane finalizes
    const int b_row   = bm + grp + ((qk >= 2) ? 8 : 0);
    const int m2w     = (m0 >> 1) + (qk & 1);         // h word index (m pair)
    const int histcol = dir * 256 + m0 + 2 * (qk & 1);
    volatile unsigned long long* barp = &g_bar[dir * 8];

    for (int t = 0; t < Ln; t++) {
        float acc[2][4];
#pragma unroll
        for (int nt = 0; nt < 2; nt++)
#pragma unroll
            for (int r = 0; r < 4; r++) acc[nt][r] = 0.0f;

        if (t > 0) {
            const uint32_t* __restrict__ hp = &g_hN[(t & 1) ^ 1][dir][0][0];
            uint32_t ab[4][4];
#define LDA(d, kb) do {                                                   \
                const uint32_t* _r0 = hp + ((kb) * 8 + qk) * Bn;          \
                const uint32_t* _r1 = hp + ((kb) * 8 + 4 + qk) * Bn;      \
                (d)[0] = __ldcg(_r0 + bm + grp);                          \
                (d)[1] = __ldcg(_r0 + bm + grp + 8);                      \
                (d)[2] = __ldcg(_r1 + bm + grp);                          \
                (d)[3] = __ldcg(_r1 + bm + grp + 8);                      \
            } while (0)
            LDA(ab[0], 0); LDA(ab[1], 1); LDA(ab[2], 2); LDA(ab[3], 3);
#pragma unroll
            for (int kb = 0; kb < 16; kb++) {
                uint32_t a[4];
                a[0] = ab[kb & 3][0]; a[1] = ab[kb & 3][1];
                a[2] = ab[kb & 3][2]; a[3] = ab[kb & 3][3];
                if (kb + 4 < 16) LDA(ab[kb & 3], kb + 4);
                uint32_t b0[2] = {B0[0][kb], B1[0][kb]};
                uint32_t b1[2] = {B0[1][kb], B1[1][kb]};
                mma_bf16(acc[0], a, b0);
                mma_bf16(acc[1], a, b1);
            }
#undef LDA
        }

        // add pre-activations (bias + input GEMM), bf16x2 packed
#pragma unroll
        for (int nt = 0; nt < 2; nt++) {
            int wrd = (nt * 2 + (qk >> 1)) * 128 + m2w;
            uint32_t w0 = g_preB[dir][t][bm + grp][wrd];
            uint32_t w1 = g_preB[dir][t][bm + grp + 8][wrd];
            acc[nt][0] += bflo(w0); acc[nt][1] += bfhi(w0);
            acc[nt][2] += bflo(w1); acc[nt][3] += bfhi(w1);
        }

        // exchange with lane^2: (i,g) <-> (f,o)
        float recv[2][4];
#pragma unroll
        for (int nt = 0; nt < 2; nt++)
#pragma unroll
            for (int r = 0; r < 4; r++)
                recv[nt][r] = __shfl_xor_sync(0xffffffffu, acc[nt][r], 2);

        const bool ig = (qk < 2);
        float h0, h1;
        {
            float i_ = ig ? acc[0][rb + 0] : recv[0][rb + 0];
            float f_ = ig ? recv[0][rb + 0] : acc[0][rb + 0];
            float g_ = ig ? acc[1][rb + 0] : recv[1][rb + 0];
            float o_ = ig ? recv[1][rb + 0] : acc[1][rb + 0];
            cst0 = sigf(f_) * cst0 + sigf(i_) * tanhfast(g_);
            h0 = sigf(o_) * tanhfast(cst0);
        }
        {
            float i_ = ig ? acc[0][rb + 1] : recv[0][rb + 1];
            float f_ = ig ? recv[0][rb + 1] : acc[0][rb + 1];
            float g_ = ig ? acc[1][rb + 1] : recv[1][rb + 1];
            float o_ = ig ? recv[1][rb + 1] : acc[1][rb + 1];
            cst1 = sigf(f_) * cst1 + sigf(i_) * tanhfast(g_);
            h1 = sigf(o_) * tanhfast(cst1);
        }

        // publish h: bf16x2 word for next step, fp32 pair to history
        __stcg(&g_hN[t & 1][dir][m2w][b_row], pack_bf16(h0, h1));
        const int rt = dir ? (Ln - 1 - t) : t;
        *(float2*)&g_hist[rt][b_row][histcol] = make_float2(h0, h1);

        if (t != Ln - 1) {
            __threadfence();
            __syncthreads();
            if (tid == 0) {
                unsigned long long v = atomicAdd(&g_bar[dir * 8], 1ULL);
                unsigned long long target = ((v >> 6) + 1ULL) << 6;   // 64 CTAs per direction
                while (*barp < target) __nanosleep(64);
            }
            __syncthreads();
        }
    }
}

// ---------------- 3) emit GEMM: emit[b][t][k] = hist[t][b][:512] @ w_emit^T + b_emit ----------------
__global__ void __launch_bounds__(256) k_emit(
    const float* __restrict__ wem, const float* __restrict__ bem)
{
    const int t = blockIdx.x;
    __shared__ float As[128][36];
    __shared__ float Bs[32][68];
    const int tid = threadIdx.x;
    const int kg = (tid & 7) << 3;
    const int bg = (tid >> 3) << 2;

    float acc[4][8];
#pragma unroll
    for (int i = 0; i < 4; i++)
#pragma unroll
        for (int j = 0; j < 8; j++) acc[i][j] = 0.0f;

    for (int j0 = 0; j0 < 512; j0 += 32) {
#pragma unroll
        for (int i = 0; i < 4; i++) {
            int idx = (i << 8) + tid;
            int b   = idx >> 3;
            int jj  = (idx & 7) << 2;
            float4 v = *(const float4*)&g_hist[t][b][j0 + jj];
            *(float4*)&As[b][jj] = v;
        }
#pragma unroll
        for (int i = 0; i < 2; i++) {
            int idx = (i << 8) + tid;
            int k   = idx >> 3;
            int jj  = (idx & 7) << 2;
            float4 w = *(const float4*)(wem + (size_t)k * 512 + j0 + jj);
            Bs[jj + 0][k] = w.x; Bs[jj + 1][k] = w.y;
            Bs[jj + 2][k] = w.z; Bs[jj + 3][k] = w.w;
        }
        __syncthreads();
#pragma unroll
        for (int jj = 0; jj < 32; jj++) {
            float a[4];
#pragma unroll
            for (int i = 0; i < 4; i++) a[i] = As[bg + i][jj];
            float w[8];
            *(float4*)(w)     = *(float4*)&Bs[jj][kg];
            *(float4*)(w + 4) = *(float4*)&Bs[jj][kg + 4];
#pragma unroll
            for (int i = 0; i < 4; i++)
#pragma unroll
                for (int k = 0; k < 8; k++)
                    acc[i][k] = fmaf(a[i], w[k], acc[i][k]);
        }
        __syncthreads();
    }
#pragma unroll
    for (int i = 0; i < 4; i++) {
        float v[8];
#pragma unroll
        for (int k = 0; k < 8; k++) v[k] = acc[i][k] + bem[kg + k];
        float* dst = &g_emit[bg + i][t][kg];
        *(float4*)dst       = *(float4*)v;
        *(float4*)(dst + 4) = *(float4*)(v + 4);
    }
}

// ---------------- 4) CRF forward + gold score ----------------
__global__ void __launch_bounds__(64) k_crf(
    const int* __restrict__ labels,
    const float* __restrict__ trans,
    float* __restrict__ out)
{
    const int b = blockIdx.x;
    const int j = threadIdx.x;
    const int lane = j & 31, wid = j >> 5;
    __shared__ float eT[64][64];
    __shared__ float ps[64];
    __shared__ float red[2];

#pragma unroll 8
    for (int i = 0; i < 64; i++)
        eT[i][j] = __expf(trans[i * 64 + j]);
    __syncthreads();

    float d = g_emit[b][0][j];
    for (int t = 1; t < Ln; t++) {
        float m = d;
#pragma unroll
        for (int o = 16; o > 0; o >>= 1)
            m = fmaxf(m, __shfl_xor_sync(0xffffffffu, m, o));
        if (lane == 0) red[wid] = m;
        __syncthreads();
        m = fmaxf(red[0], red[1]);
        float p = __expf(d - m);
        ps[j] = p;
        __syncthreads();
        float s0 = 0.0f, s1 = 0.0f, s2 = 0.0f, s3 = 0.0f;
#pragma unroll
        for (int i = 0; i < 64; i += 4) {
            s0 = fmaf(ps[i + 0], eT[i + 0][j], s0);
            s1 = fmaf(ps[i + 1], eT[i + 1][j], s1);
            s2 = fmaf(ps[i + 2], eT[i + 2][j], s2);
            s3 = fmaf(ps[i + 3], eT[i + 3][j], s3);
        }
        float s = (s0 + s1) + (s2 + s3);
        d = g_emit[b][t][j] + m + __logf(s);
        __syncthreads();
    }

    float m2 = d;
#pragma unroll
    for (int o = 16; o > 0; o >>= 1)
        m2 = fmaxf(m2, __shfl_xor_sync(0xffffffffu, m2, o));
    if (lane == 0) red[wid] = m2;
    __syncthreads();
    m2 = fmaxf(red[0], red[1]);
    __syncthreads();
    float sp = __expf(d - m2);
#pragma unroll
    for (int o = 16; o > 0; o >>= 1)
        sp += __shfl_xor_sync(0xffffffffu, sp, o);
    if (lane == 0) red[wid] = sp;
    __syncthreads();
    float logz = m2 + __logf(red[0] + red[1]);
    __syncthreads();

    float gold = 0.0f;
    for (int t = j; t < Ln; t += 64) {
        int lab = labels[b * Ln + t];
        gold += g_emit[b][t][lab];
        if (t < Ln - 1) {
            int lab2 = labels[b * Ln + t + 1];
            gold += trans[lab * 64 + lab2];
        }
    }
#pragma unroll
    for (int o = 16; o > 0; o >>= 1)
        gold += __shfl_xor_sync(0xffffffffu, gold, o);
    if (lane == 0) red[wid] = gold;
    __syncthreads();
    gold = red[0] + red[1];

    if (j == 0) out[b] = logz - gold;
}

// ---------------- launch ----------------
extern "C" void kernel_launch(void* const* d_in, const int* in_sizes, int n_in,
                              void* d_out, int out_size)
{
    const float* x     = (const float*)d_in[0];
    const int*   lab   = (const int*)d_in[1];
    const float* wihf  = (const float*)d_in[2];
    const float* whhf  = (const float*)d_in[3];
    const float* bihf  = (const float*)d_in[4];
    const float* bhhf  = (const float*)d_in[5];
    const float* wihb  = (const float*)d_in[6];
    const float* whhb  = (const float*)d_in[7];
    const float* bihb  = (const float*)d_in[8];
    const float* bhhb  = (const float*)d_in[9];
    const float* wem   = (const float*)d_in[10];
    const float* bem   = (const float*)d_in[11];
    const float* trans = (const float*)d_in[12];
    float* out = (float*)d_out;

    dim3 gg(8, 512, 2);
    k_gemm_bf16<<<gg, 256>>>(x, wihf, wihb, bihf, bhhf, bihb, bhhb);
    k_lstm2<<<128, 256>>>(whhf, whhb);
    k_emit<<<512, 256>>>(wem, bem);
    k_crf<<<128, 64>>>(lab, trans, out);
}